// round 14
// baseline (speedup 1.0000x reference)
#include <cuda_runtime.h>
#include <cuda_bf16.h>

#define K_FEAT 4096
#define N_CTRL 256
#define M_INT  254       // interior knots
#define HALF   6         // tap half-width; truncation ~rho^7 (rel_err 3.3e-5 measured)
#define WINR   16        // value-row window per block: rows [s-7, s+8]

// Tap weight of the truncated closed-form inverse of the uniform [1 4 1]
// system: w(g,j) = ACP*(rho^|j-p| - rho^(j+p+2) - rho^(2m-j-p)), p=g-1,
// rho=-(2-sqrt(3)), ACP=(1/(2*sqrt(3)))*6/h^2. Powers via exp2f (MUFU).
__device__ __forceinline__ float tapw(int g, int j) {
    const int p = g - 1;
    const int d = j - p;
    if (g < 1 || g > M_INT || j < 0 || j >= M_INT || d > HALF || d < -HALF) return 0.0f;
    const float L   = -1.8999686269529529f;                       // log2(2-sqrt(3))
    const float ACP = 0.28867513459481288f * 6.0f * 255.0f * 255.0f;
    int e0 = d < 0 ? -d : d;
    int e1 = j + p + 2;
    int e2 = 2 * M_INT - j - p;
    float t0 = exp2f(L * (float)e0); if (e0 & 1) t0 = -t0;
    float t1 = exp2f(L * (float)e1); if (e1 & 1) t1 = -t1;
    float t2 = exp2f(L * (float)e2); if (e2 & 1) t2 = -t2;
    return ACP * (t0 - t1 - t2);
}

__device__ __forceinline__ float4 load_row_clamped(const float* __restrict__ values,
                                                   int row, int k) {
    int r = row < 0 ? 0 : (row > N_CTRL - 1 ? N_CTRL - 1 : row);
    return *reinterpret_cast<const float4*>(values + (size_t)r * K_FEAT + k);
}

// ---------------------------------------------------------------------------
// Single fused kernel. The second-difference operator is folded into the
// weights (exact algebra): gamma_g = sum_r c_g(r) * v[r] with
// c(r) = w(r) - 2 w(r-1) + w(r-2), over a 16-row window [s-7, s+8].
// Prologue = 32 threads build coeffs in parallel (exp2f) + 16 unconditional
// clamped loads + 128 FMA; y0/y1 captured from the loop's own u=7/8 loads.
// Then the proven eval body streams the segment's ~32 output rows.
// ---------------------------------------------------------------------------
__global__ void __launch_bounds__(256) spline_fused_kernel(
    const float* __restrict__ values, float* __restrict__ out, int ne1) {

    __shared__ float C0[WINR], C1[WINR];

    const int tid = threadIdx.x;
    const int s   = blockIdx.y;               // segment, 0..254
    const int rlo = s - 7;                    // first value row of window

    if (tid < 2 * WINR) {
        const int g = s + (tid >> 4);         // tid<16 -> gamma row s ; else s+1
        const int r = rlo + (tid & 15);
        float c = tapw(g, r) - 2.0f * tapw(g, r - 1) + tapw(g, r - 2);
        if (tid < WINR) C0[tid] = c; else C1[tid & 15] = c;
    }
    __syncthreads();

    const int k = (blockIdx.x * 256 + tid) * 4;

    float4 q0 = make_float4(0.f, 0.f, 0.f, 0.f);
    float4 q1 = make_float4(0.f, 0.f, 0.f, 0.f);
    float4 y0, y1;

    #pragma unroll
    for (int u = 0; u < WINR; u++) {
        float4 v = load_row_clamped(values, rlo + u, k);   // unconditional
        if (u == 7) y0 = v;                                // row s
        if (u == 8) y1 = v;                                // row s+1
        float c0 = C0[u], c1 = C1[u];
        q0.x = fmaf(c0, v.x, q0.x); q0.y = fmaf(c0, v.y, q0.y);
        q0.z = fmaf(c0, v.z, q0.z); q0.w = fmaf(c0, v.w, q0.w);
        q1.x = fmaf(c1, v.x, q1.x); q1.y = fmaf(c1, v.y, q1.y);
        q1.z = fmaf(c1, v.z, q1.z); q1.w = fmaf(c1, v.w, q1.w);
    }

    // --- evaluate & stream this segment's rows ---
    const int jstart = (s * ne1 + 254) / 255;                // ceil(s*ne1/255)
    const int jend   = (s < 254) ? ((s + 1) * ne1 + 254) / 255 - 1 : ne1;

    const float inv_ne1 = 1.0f / (float)ne1;
    const float w = 1.0f / (6.0f * 255.0f * 255.0f);         // h^2/6
    const int base = s * ne1;

    #pragma unroll 4
    for (int j = jstart; j <= jend; j++) {
        float b  = (float)(j * 255 - base) * inv_ne1;        // in [0,1]
        float a  = 1.0f - b;
        float wa = (a * a * a - a) * w;
        float wb = (b * b * b - b) * w;
        float4 o;
        o.x = fmaf(a, y0.x, fmaf(b, y1.x, fmaf(wa, q0.x, wb * q1.x)));
        o.y = fmaf(a, y0.y, fmaf(b, y1.y, fmaf(wa, q0.y, wb * q1.y)));
        o.z = fmaf(a, y0.z, fmaf(b, y1.z, fmaf(wa, q0.z, wb * q1.z)));
        o.w = fmaf(a, y0.w, fmaf(b, y1.w, fmaf(wa, q0.w, wb * q1.w)));
        __stcs(reinterpret_cast<float4*>(out + (size_t)j * K_FEAT + k), o);
    }
}

extern "C" void kernel_launch(void* const* d_in, const int* in_sizes, int n_in,
                              void* d_out, int out_size) {
    const float* values = (const float*)d_in[0];
    float* out = (float*)d_out;

    const int n_eval = out_size / K_FEAT;
    const int ne1 = n_eval - 1;

    dim3 grid(K_FEAT / (256 * 4), N_CTRL - 1);               // (4, 255)
    spline_fused_kernel<<<grid, 256>>>(values, out, ne1);
}